// round 3
// baseline (speedup 1.0000x reference)
#include <cuda_runtime.h>
#include <cuda_bf16.h>
#include <math.h>

// Problem constants (fixed by the dataset)
#define NN 131072        // nodes
#define NE 2097152       // edges

// ---------------------------------------------------------------------------
// Scratch (allocation-free rule: __device__ globals)
// ---------------------------------------------------------------------------
__device__ __align__(16) float g_h0[NN * 16];   // after Linear(16,16)
__device__ __align__(16) float g_h1[NN * 32];   // after block3
__device__ __align__(16) float g_h2[NN * 64];   // after block2
__device__ __align__(16) float g_agg[NN * 64];  // scatter buffer (max C=64)
__device__ __align__(16) float g_deg[NN];       // degree, then 1/max(deg,1)

// ---------------------------------------------------------------------------
// Utility kernels
// ---------------------------------------------------------------------------
__global__ void zero_kernel(float4* __restrict__ p, int n4) {
    int i = blockIdx.x * blockDim.x + threadIdx.x;
    if (i < n4) p[i] = make_float4(0.f, 0.f, 0.f, 0.f);
}

__global__ void deg_kernel(const int* __restrict__ dst, float* __restrict__ deg) {
    int e = blockIdx.x * blockDim.x + threadIdx.x;
    if (e < NE) atomicAdd(&deg[dst[e]], 1.0f);
}

__global__ void rdeg_kernel(float* __restrict__ deg) {
    int i = blockIdx.x * blockDim.x + threadIdx.x;
    if (i < NN) deg[i] = 1.0f / fmaxf(deg[i], 1.0f);
}

// ---------------------------------------------------------------------------
// Edge scatter: agg[dst] += h[src], vectorized float4 per thread,
// red.global.add.v4.f32 (no-return vector reduction, sm_90+).
// C4 = channels/4 (power of two).
// ---------------------------------------------------------------------------
template <int C4>
__global__ void scatter_kernel(const int* __restrict__ src,
                               const int* __restrict__ dst,
                               const float* __restrict__ h,
                               float* __restrict__ agg) {
    int idx = blockIdx.x * blockDim.x + threadIdx.x;   // total = NE*C4 < 2^31
    if (idx >= NE * C4) return;
    int e = idx >> (C4 == 4 ? 2 : (C4 == 8 ? 3 : 4));
    int c = idx & (C4 - 1);
    int s = src[e];
    int d = dst[e];
    float4 v = reinterpret_cast<const float4*>(h)[s * C4 + c];
    float4* p = reinterpret_cast<float4*>(agg) + d * C4 + c;
    asm volatile("red.global.add.v4.f32 [%0], {%1, %2, %3, %4};"
                 :: "l"(p), "f"(v.x), "f"(v.y), "f"(v.z), "f"(v.w)
                 : "memory");
}

// ---------------------------------------------------------------------------
// Fused combine: out = act( h @ Wself + (agg * rdeg) @ Wnbr + b )
// Block = 256 threads, BN = 64 nodes per block.
// Thread layout: TX = COUT/4 threads over outputs (4 outs each, float4),
//                TY = 256/TX over nodes, NT = 64/TY nodes per thread.
// Weights [Wself;Wnbr] staged to shared once per block; inputs staged per block.
// ACT: 0 = none, 1 = relu, 2 = sigmoid.
// ---------------------------------------------------------------------------
template <int ACT>
__device__ __forceinline__ float actf(float x) {
    if (ACT == 1) return fmaxf(x, 0.f);
    if (ACT == 2) return 1.0f / (1.0f + __expf(-x));
    return x;
}

template <int CIN, int COUT, bool NBR, int ACT>
__global__ void combine_kernel(const float* __restrict__ h,
                               const float* __restrict__ agg,
                               const float* __restrict__ rdeg,
                               const float* __restrict__ Wself,
                               const float* __restrict__ Wnbr,
                               const float* __restrict__ bias,
                               float* __restrict__ out) {
    constexpr int K  = NBR ? 2 * CIN : CIN;
    constexpr int BN = 64;
    constexpr int TX = COUT / 4;
    constexpr int TY = 256 / TX;
    constexpr int NT = BN / TY;

    extern __shared__ float sm[];
    float* Ws = sm;                    // [K][COUT]
    float* Bs = Ws + K * COUT;         // [COUT]
    float* Is = Bs + COUT;             // [BN][K+1] (pad to kill bank conflicts)

    const int tid = threadIdx.x;

    // Stage combined weight matrix + bias
    for (int i = tid; i < K * COUT; i += 256) {
        int k = i / COUT, c = i % COUT;
        Ws[i] = (k < CIN) ? Wself[k * COUT + c] : Wnbr[(k - CIN) * COUT + c];
    }
    if (tid < COUT) Bs[tid] = bias[tid];

    const int base = blockIdx.x * BN;

    // Stage inputs: [h_row | (agg_row * rdeg)]
    for (int i = tid; i < BN * K; i += 256) {
        int n = i / K, k = i % K;
        int node = base + n;
        float v;
        if (!NBR || k < CIN) v = h[node * CIN + k];
        else                 v = agg[node * CIN + (k - CIN)] * rdeg[node];
        Is[n * (K + 1) + k] = v;
    }
    __syncthreads();

    const int tx = tid % TX;
    const int ny = tid / TX;

    float acc[NT][4];
    float4 b4 = *reinterpret_cast<const float4*>(&Bs[tx * 4]);
#pragma unroll
    for (int i = 0; i < NT; i++) {
        acc[i][0] = b4.x; acc[i][1] = b4.y; acc[i][2] = b4.z; acc[i][3] = b4.w;
    }

#pragma unroll 8
    for (int k = 0; k < K; k++) {
        float4 w = *reinterpret_cast<const float4*>(&Ws[k * COUT + tx * 4]);
#pragma unroll
        for (int i = 0; i < NT; i++) {
            float v = Is[(ny * NT + i) * (K + 1) + k];
            acc[i][0] += v * w.x;
            acc[i][1] += v * w.y;
            acc[i][2] += v * w.z;
            acc[i][3] += v * w.w;
        }
    }

#pragma unroll
    for (int i = 0; i < NT; i++) {
        int node = base + ny * NT + i;
        float4 o;
        o.x = actf<ACT>(acc[i][0]);
        o.y = actf<ACT>(acc[i][1]);
        o.z = actf<ACT>(acc[i][2]);
        o.w = actf<ACT>(acc[i][3]);
        *reinterpret_cast<float4*>(&out[node * COUT + tx * 4]) = o;
    }
}

// ---------------------------------------------------------------------------
// Launch
// ---------------------------------------------------------------------------
static inline int smem_bytes(int K, int COUT) {
    return (K * COUT + COUT + 64 * (K + 1)) * (int)sizeof(float);
}

extern "C" void kernel_launch(void* const* d_in, const int* in_sizes, int n_in,
                              void* d_out, int out_size) {
    const float* x     = (const float*)d_in[0];
    const int*   ei    = (const int*)d_in[1];      // [2, E]
    // d_in[2] = batch (unused)
    const float* W_lin = (const float*)d_in[3];
    const float* b_lin = (const float*)d_in[4];
    const float* Ws3   = (const float*)d_in[5];
    const float* Wn3   = (const float*)d_in[6];
    const float* b3    = (const float*)d_in[7];
    const float* Ws2   = (const float*)d_in[8];
    const float* Wn2   = (const float*)d_in[9];
    const float* b2    = (const float*)d_in[10];
    const float* Ws1   = (const float*)d_in[11];
    const float* Wn1   = (const float*)d_in[12];
    const float* b1    = (const float*)d_in[13];
    float* out = (float*)d_out;

    const int* src = ei;
    const int* dst = ei + NE;

    float *h0, *h1, *h2, *agg, *deg;
    cudaGetSymbolAddress((void**)&h0,  g_h0);
    cudaGetSymbolAddress((void**)&h1,  g_h1);
    cudaGetSymbolAddress((void**)&h2,  g_h2);
    cudaGetSymbolAddress((void**)&agg, g_agg);
    cudaGetSymbolAddress((void**)&deg, g_deg);

    // Allow >48KB dynamic smem for the big combine (64KB weights + 33KB inputs)
    cudaFuncSetAttribute((const void*)combine_kernel<64, 128, true, 2>,
                         cudaFuncAttributeMaxDynamicSharedMemorySize, 112 * 1024);

    const int T = 256;
    const int NB = NN / 64;   // combine grid

    // Degree (shared by all layers)
    zero_kernel<<<(NN / 4 + T - 1) / T, T>>>((float4*)deg, NN / 4);
    deg_kernel<<<NE / T, T>>>(dst, deg);
    rdeg_kernel<<<NN / T, T>>>(deg);

    // Linear(16,16)
    combine_kernel<16, 16, false, 0><<<NB, T, smem_bytes(16, 16)>>>(
        x, nullptr, nullptr, W_lin, nullptr, b_lin, h0);

    // Block3: 16 -> 32, relu
    zero_kernel<<<(NN * 16 / 4) / T, T>>>((float4*)agg, NN * 16 / 4);
    scatter_kernel<4><<<(NE * 4) / T, T>>>(src, dst, h0, agg);
    combine_kernel<16, 32, true, 1><<<NB, T, smem_bytes(32, 32)>>>(
        h0, agg, deg, Ws3, Wn3, b3, h1);

    // Block2: 32 -> 64, relu
    zero_kernel<<<(NN * 32 / 4) / T, T>>>((float4*)agg, NN * 32 / 4);
    scatter_kernel<8><<<(NE * 8) / T, T>>>(src, dst, h1, agg);
    combine_kernel<32, 64, true, 1><<<NB, T, smem_bytes(64, 64)>>>(
        h1, agg, deg, Ws2, Wn2, b2, h2);

    // Block1: 64 -> 128, sigmoid -> d_out
    zero_kernel<<<(NN * 64 / 4) / T, T>>>((float4*)agg, NN * 64 / 4);
    scatter_kernel<16><<<(NE * 16) / T, T>>>(src, dst, h2, agg);
    combine_kernel<64, 128, true, 2><<<NB, T, smem_bytes(128, 128)>>>(
        h2, agg, deg, Ws1, Wn1, b1, out);
}

// round 4
// speedup vs baseline: 1.1991x; 1.1991x over previous
#include <cuda_runtime.h>
#include <cuda_bf16.h>
#include <math.h>

// Problem constants (fixed by the dataset)
#define NN 131072        // nodes
#define NE 2097152       // edges

// ---------------------------------------------------------------------------
// Scratch (allocation-free rule: __device__ globals)
// ---------------------------------------------------------------------------
__device__ __align__(16) float g_h0[NN * 16];   // after Linear(16,16)
__device__ __align__(16) float g_h1[NN * 32];   // after block3
__device__ __align__(16) float g_h2[NN * 64];   // after block2
__device__ __align__(16) float g_agg[NN * 64];  // gather output (max C=64)
__device__ __align__(16) float g_rdeg[NN];      // 1/max(deg,1)

__device__ int g_deg[NN];        // integer in-degree
__device__ int g_rowoff[NN];     // exclusive prefix sum of degree (CSR row start)
__device__ int g_cursor[NN];     // fill cursors
__device__ int g_col[NE];        // CSR column (src node per incoming edge)
__device__ int g_bsum[512];      // scan block sums

// ---------------------------------------------------------------------------
// CSR construction
// ---------------------------------------------------------------------------
__global__ void zero2_int(int* __restrict__ a, int* __restrict__ b) {
    int i = blockIdx.x * blockDim.x + threadIdx.x;
    if (i < NN) { a[i] = 0; b[i] = 0; }
}

__global__ void deg_kernel(const int* __restrict__ dst, int* __restrict__ deg) {
    int e = blockIdx.x * blockDim.x + threadIdx.x;
    if (e < NE) atomicAdd(&deg[dst[e]], 1);
}

// Per-block exclusive scan of 256 elements; block totals to bsum.
__global__ void scanA(const int* __restrict__ deg, int* __restrict__ part,
                      int* __restrict__ bsum) {
    __shared__ int s[256];
    int t = threadIdx.x;
    int i = blockIdx.x * 256 + t;
    int v = deg[i];
    s[t] = v;
    __syncthreads();
    for (int o = 1; o < 256; o <<= 1) {
        int u = (t >= o) ? s[t - o] : 0;
        __syncthreads();
        s[t] += u;
        __syncthreads();
    }
    part[i] = s[t] - v;                       // exclusive
    if (t == 255) bsum[blockIdx.x] = s[255];  // inclusive total
}

// Exclusive scan of the 512 block sums (single block).
__global__ void scanB(int* __restrict__ bsum) {
    __shared__ int s[512];
    int t = threadIdx.x;
    int v = bsum[t];
    s[t] = v;
    __syncthreads();
    for (int o = 1; o < 512; o <<= 1) {
        int u = (t >= o) ? s[t - o] : 0;
        __syncthreads();
        s[t] += u;
        __syncthreads();
    }
    bsum[t] = s[t] - v;
}

__global__ void scanC(int* __restrict__ part, const int* __restrict__ bsum) {
    int i = blockIdx.x * 256 + threadIdx.x;
    part[i] += bsum[blockIdx.x];
}

__global__ void rdeg_kernel(const int* __restrict__ deg, float* __restrict__ rdeg) {
    int i = blockIdx.x * blockDim.x + threadIdx.x;
    if (i < NN) rdeg[i] = 1.0f / fmaxf((float)deg[i], 1.0f);
}

__global__ void fill_kernel(const int* __restrict__ src, const int* __restrict__ dst,
                            const int* __restrict__ rowoff, int* __restrict__ cursor,
                            int* __restrict__ col) {
    int e = blockIdx.x * blockDim.x + threadIdx.x;
    if (e >= NE) return;
    int d = dst[e];
    int pos = rowoff[d] + atomicAdd(&cursor[d], 1);
    col[pos] = src[e];
}

// ---------------------------------------------------------------------------
// CSR gather: agg[n] = (1/max(deg,1)) * sum_{s in nbrs(n)} h[s]
// One warp per node. Lanes tiled as (neighbor_slot x C4) float4 chunks,
// shfl-reduced across slots. Pure reads, no atomics, no pre-zero needed.
// ---------------------------------------------------------------------------
template <int C4>
__global__ void gather_kernel(const int* __restrict__ rowoff,
                              const int* __restrict__ deg,
                              const int* __restrict__ col,
                              const float* __restrict__ rdeg,
                              const float* __restrict__ h,
                              float* __restrict__ agg) {
    constexpr int SLOTS = 32 / C4;
    int warp = (blockIdx.x * blockDim.x + threadIdx.x) >> 5;
    if (warp >= NN) return;
    int lane = threadIdx.x & 31;
    int slot = lane / C4;
    int c    = lane % C4;

    int start = rowoff[warp];
    int d     = deg[warp];

    const float4* h4 = reinterpret_cast<const float4*>(h);
    float4 acc = make_float4(0.f, 0.f, 0.f, 0.f);

    for (int ni = slot; ni < d; ni += SLOTS) {
        int nbr = col[start + ni];          // broadcast across the C4 lanes
        float4 v = h4[nbr * C4 + c];
        acc.x += v.x; acc.y += v.y; acc.z += v.z; acc.w += v.w;
    }

#pragma unroll
    for (int off = 16; off >= C4; off >>= 1) {
        acc.x += __shfl_xor_sync(0xFFFFFFFFu, acc.x, off);
        acc.y += __shfl_xor_sync(0xFFFFFFFFu, acc.y, off);
        acc.z += __shfl_xor_sync(0xFFFFFFFFu, acc.z, off);
        acc.w += __shfl_xor_sync(0xFFFFFFFFu, acc.w, off);
    }

    if (lane < C4) {
        float r = rdeg[warp];
        reinterpret_cast<float4*>(agg)[warp * C4 + c] =
            make_float4(acc.x * r, acc.y * r, acc.z * r, acc.w * r);
    }
}

// ---------------------------------------------------------------------------
// Fused combine: out = act( h @ Wself + agg @ Wnbr + b )   (agg pre-normalized)
// Block = 256 threads, BN = 64 nodes per block.
// ACT: 0 = none, 1 = relu, 2 = sigmoid.
// ---------------------------------------------------------------------------
template <int ACT>
__device__ __forceinline__ float actf(float x) {
    if (ACT == 1) return fmaxf(x, 0.f);
    if (ACT == 2) return 1.0f / (1.0f + __expf(-x));
    return x;
}

template <int CIN, int COUT, bool NBR, int ACT>
__global__ void combine_kernel(const float* __restrict__ h,
                               const float* __restrict__ agg,
                               const float* __restrict__ Wself,
                               const float* __restrict__ Wnbr,
                               const float* __restrict__ bias,
                               float* __restrict__ out) {
    constexpr int K  = NBR ? 2 * CIN : CIN;
    constexpr int BN = 64;
    constexpr int TX = COUT / 4;
    constexpr int TY = 256 / TX;
    constexpr int NT = BN / TY;

    extern __shared__ float sm[];
    float* Ws = sm;                    // [K][COUT]
    float* Bs = Ws + K * COUT;         // [COUT]
    float* Is = Bs + COUT;             // [BN][K+1]

    const int tid = threadIdx.x;

    for (int i = tid; i < K * COUT; i += 256) {
        int k = i / COUT, c = i % COUT;
        Ws[i] = (k < CIN) ? Wself[k * COUT + c] : Wnbr[(k - CIN) * COUT + c];
    }
    if (tid < COUT) Bs[tid] = bias[tid];

    const int base = blockIdx.x * BN;

    for (int i = tid; i < BN * K; i += 256) {
        int n = i / K, k = i % K;
        int node = base + n;
        float v;
        if (!NBR || k < CIN) v = h[node * CIN + k];
        else                 v = agg[node * CIN + (k - CIN)];
        Is[n * (K + 1) + k] = v;
    }
    __syncthreads();

    const int tx = tid % TX;
    const int ny = tid / TX;

    float acc[NT][4];
    float4 b4 = *reinterpret_cast<const float4*>(&Bs[tx * 4]);
#pragma unroll
    for (int i = 0; i < NT; i++) {
        acc[i][0] = b4.x; acc[i][1] = b4.y; acc[i][2] = b4.z; acc[i][3] = b4.w;
    }

#pragma unroll 8
    for (int k = 0; k < K; k++) {
        float4 w = *reinterpret_cast<const float4*>(&Ws[k * COUT + tx * 4]);
#pragma unroll
        for (int i = 0; i < NT; i++) {
            float v = Is[(ny * NT + i) * (K + 1) + k];
            acc[i][0] += v * w.x;
            acc[i][1] += v * w.y;
            acc[i][2] += v * w.z;
            acc[i][3] += v * w.w;
        }
    }

#pragma unroll
    for (int i = 0; i < NT; i++) {
        int node = base + ny * NT + i;
        float4 o;
        o.x = actf<ACT>(acc[i][0]);
        o.y = actf<ACT>(acc[i][1]);
        o.z = actf<ACT>(acc[i][2]);
        o.w = actf<ACT>(acc[i][3]);
        *reinterpret_cast<float4*>(&out[node * COUT + tx * 4]) = o;
    }
}

// ---------------------------------------------------------------------------
// Launch
// ---------------------------------------------------------------------------
static inline int smem_bytes(int K, int COUT) {
    return (K * COUT + COUT + 64 * (K + 1)) * (int)sizeof(float);
}

extern "C" void kernel_launch(void* const* d_in, const int* in_sizes, int n_in,
                              void* d_out, int out_size) {
    const float* x     = (const float*)d_in[0];
    const int*   ei    = (const int*)d_in[1];      // [2, E]
    // d_in[2] = batch (unused)
    const float* W_lin = (const float*)d_in[3];
    const float* b_lin = (const float*)d_in[4];
    const float* Ws3   = (const float*)d_in[5];
    const float* Wn3   = (const float*)d_in[6];
    const float* b3    = (const float*)d_in[7];
    const float* Ws2   = (const float*)d_in[8];
    const float* Wn2   = (const float*)d_in[9];
    const float* b2    = (const float*)d_in[10];
    const float* Ws1   = (const float*)d_in[11];
    const float* Wn1   = (const float*)d_in[12];
    const float* b1    = (const float*)d_in[13];
    float* out = (float*)d_out;

    const int* src = ei;
    const int* dst = ei + NE;

    float *h0, *h1, *h2, *agg, *rdeg;
    int *deg, *rowoff, *cursor, *col, *bsum;
    cudaGetSymbolAddress((void**)&h0,     g_h0);
    cudaGetSymbolAddress((void**)&h1,     g_h1);
    cudaGetSymbolAddress((void**)&h2,     g_h2);
    cudaGetSymbolAddress((void**)&agg,    g_agg);
    cudaGetSymbolAddress((void**)&rdeg,   g_rdeg);
    cudaGetSymbolAddress((void**)&deg,    g_deg);
    cudaGetSymbolAddress((void**)&rowoff, g_rowoff);
    cudaGetSymbolAddress((void**)&cursor, g_cursor);
    cudaGetSymbolAddress((void**)&col,    g_col);
    cudaGetSymbolAddress((void**)&bsum,   g_bsum);

    cudaFuncSetAttribute((const void*)combine_kernel<64, 128, true, 2>,
                         cudaFuncAttributeMaxDynamicSharedMemorySize, 112 * 1024);

    const int T  = 256;
    const int NB = NN / 64;          // combine grid
    const int GW = NN * 32 / T;      // gather grid (1 warp/node)

    // ---- CSR build (per launch; graph-capturable, ~20-25us) ----
    zero2_int<<<NN / T, T>>>(deg, cursor);
    deg_kernel<<<NE / T, T>>>(dst, deg);
    scanA<<<512, 256>>>(deg, rowoff, bsum);
    scanB<<<1, 512>>>(bsum);
    scanC<<<512, 256>>>(rowoff, bsum);
    rdeg_kernel<<<NN / T, T>>>(deg, rdeg);
    fill_kernel<<<NE / T, T>>>(src, dst, rowoff, cursor, col);

    // ---- Linear(16,16) ----
    combine_kernel<16, 16, false, 0><<<NB, T, smem_bytes(16, 16)>>>(
        x, nullptr, W_lin, nullptr, b_lin, h0);

    // ---- Block3: 16 -> 32, relu ----
    gather_kernel<4><<<GW, T>>>(rowoff, deg, col, rdeg, h0, agg);
    combine_kernel<16, 32, true, 1><<<NB, T, smem_bytes(32, 32)>>>(
        h0, agg, Ws3, Wn3, b3, h1);

    // ---- Block2: 32 -> 64, relu ----
    gather_kernel<8><<<GW, T>>>(rowoff, deg, col, rdeg, h1, agg);
    combine_kernel<32, 64, true, 1><<<NB, T, smem_bytes(64, 64)>>>(
        h1, agg, Ws2, Wn2, b2, h2);

    // ---- Block1: 64 -> 128, sigmoid -> d_out ----
    gather_kernel<16><<<GW, T>>>(rowoff, deg, col, rdeg, h2, agg);
    combine_kernel<64, 128, true, 2><<<NB, T, smem_bytes(128, 128)>>>(
        h2, agg, Ws1, Wn1, b1, out);
}

// round 5
// speedup vs baseline: 1.2668x; 1.0565x over previous
#include <cuda_runtime.h>
#include <cuda_bf16.h>
#include <mma.h>
#include <math.h>

using namespace nvcuda;

// Problem constants (fixed by the dataset)
#define NN 131072        // nodes
#define NE 2097152       // edges

// ---------------------------------------------------------------------------
// Scratch (allocation-free rule: __device__ globals)
// ---------------------------------------------------------------------------
__device__ __align__(16) float g_h0[NN * 16];   // after Linear(16,16)
__device__ __align__(16) float g_h1[NN * 32];   // after block3
__device__ __align__(16) float g_h2[NN * 64];   // after block2
__device__ __align__(16) float g_agg[NN * 64];  // gather output (max C=64)
__device__ __align__(16) float g_rdeg[NN];      // 1/max(deg,1)

__device__ int g_deg[NN];        // integer in-degree
__device__ int g_rowoff[NN];     // exclusive prefix sum of degree (CSR row start)
__device__ int g_cursor[NN];     // fill cursors
__device__ int g_col[NE];        // CSR column (src node per incoming edge)
__device__ int g_bsum[512];      // scan block sums

// ---------------------------------------------------------------------------
// CSR construction
// ---------------------------------------------------------------------------
__global__ void zero2_int(int* __restrict__ a, int* __restrict__ b) {
    int i = blockIdx.x * blockDim.x + threadIdx.x;
    if (i < NN) { a[i] = 0; b[i] = 0; }
}

__global__ void deg_kernel(const int* __restrict__ dst, int* __restrict__ deg) {
    int e = blockIdx.x * blockDim.x + threadIdx.x;
    if (e < NE) atomicAdd(&deg[dst[e]], 1);
}

// Per-block exclusive scan of 256 elements; block totals to bsum.
__global__ void scanA(const int* __restrict__ deg, int* __restrict__ part,
                      int* __restrict__ bsum) {
    __shared__ int s[256];
    int t = threadIdx.x;
    int i = blockIdx.x * 256 + t;
    int v = deg[i];
    s[t] = v;
    __syncthreads();
    for (int o = 1; o < 256; o <<= 1) {
        int u = (t >= o) ? s[t - o] : 0;
        __syncthreads();
        s[t] += u;
        __syncthreads();
    }
    part[i] = s[t] - v;                       // exclusive
    if (t == 255) bsum[blockIdx.x] = s[255];  // inclusive total
}

// Exclusive scan of the 512 block sums (single block).
__global__ void scanB(int* __restrict__ bsum) {
    __shared__ int s[512];
    int t = threadIdx.x;
    int v = bsum[t];
    s[t] = v;
    __syncthreads();
    for (int o = 1; o < 512; o <<= 1) {
        int u = (t >= o) ? s[t - o] : 0;
        __syncthreads();
        s[t] += u;
        __syncthreads();
    }
    bsum[t] = s[t] - v;
}

__global__ void scanC(int* __restrict__ part, const int* __restrict__ bsum) {
    int i = blockIdx.x * 256 + threadIdx.x;
    part[i] += bsum[blockIdx.x];
}

__global__ void rdeg_kernel(const int* __restrict__ deg, float* __restrict__ rdeg) {
    int i = blockIdx.x * blockDim.x + threadIdx.x;
    if (i < NN) rdeg[i] = 1.0f / fmaxf((float)deg[i], 1.0f);
}

__global__ void fill_kernel(const int* __restrict__ src, const int* __restrict__ dst,
                            const int* __restrict__ rowoff, int* __restrict__ cursor,
                            int* __restrict__ col) {
    int e = blockIdx.x * blockDim.x + threadIdx.x;
    if (e >= NE) return;
    int d = dst[e];
    int pos = rowoff[d] + atomicAdd(&cursor[d], 1);
    col[pos] = src[e];
}

// ---------------------------------------------------------------------------
// CSR gather: agg[n] = (1/max(deg,1)) * sum_{s in nbrs(n)} h[s]
// One warp per node, (neighbor_slot x C4) float4 lanes, shfl-reduce.
// ---------------------------------------------------------------------------
template <int C4>
__global__ void gather_kernel(const int* __restrict__ rowoff,
                              const int* __restrict__ deg,
                              const int* __restrict__ col,
                              const float* __restrict__ rdeg,
                              const float* __restrict__ h,
                              float* __restrict__ agg) {
    constexpr int SLOTS = 32 / C4;
    int warp = (blockIdx.x * blockDim.x + threadIdx.x) >> 5;
    if (warp >= NN) return;
    int lane = threadIdx.x & 31;
    int slot = lane / C4;
    int c    = lane % C4;

    int start = rowoff[warp];
    int d     = deg[warp];

    const float4* h4 = reinterpret_cast<const float4*>(h);
    float4 acc = make_float4(0.f, 0.f, 0.f, 0.f);

    for (int ni = slot; ni < d; ni += SLOTS) {
        int nbr = col[start + ni];
        float4 v = h4[nbr * C4 + c];
        acc.x += v.x; acc.y += v.y; acc.z += v.z; acc.w += v.w;
    }

#pragma unroll
    for (int off = 16; off >= C4; off >>= 1) {
        acc.x += __shfl_xor_sync(0xFFFFFFFFu, acc.x, off);
        acc.y += __shfl_xor_sync(0xFFFFFFFFu, acc.y, off);
        acc.z += __shfl_xor_sync(0xFFFFFFFFu, acc.z, off);
        acc.w += __shfl_xor_sync(0xFFFFFFFFu, acc.w, off);
    }

    if (lane < C4) {
        float r = rdeg[warp];
        reinterpret_cast<float4*>(agg)[warp * C4 + c] =
            make_float4(acc.x * r, acc.y * r, acc.z * r, acc.w * r);
    }
}

// ---------------------------------------------------------------------------
// SIMT fused combine (small layers): out = act(h @ Wself + agg @ Wnbr + b)
// ---------------------------------------------------------------------------
template <int ACT>
__device__ __forceinline__ float actf(float x) {
    if (ACT == 1) return fmaxf(x, 0.f);
    if (ACT == 2) return 1.0f / (1.0f + __expf(-x));
    return x;
}

template <int CIN, int COUT, bool NBR, int ACT>
__global__ void combine_kernel(const float* __restrict__ h,
                               const float* __restrict__ agg,
                               const float* __restrict__ Wself,
                               const float* __restrict__ Wnbr,
                               const float* __restrict__ bias,
                               float* __restrict__ out) {
    constexpr int K  = NBR ? 2 * CIN : CIN;
    constexpr int BN = 64;
    constexpr int TX = COUT / 4;
    constexpr int TY = 256 / TX;
    constexpr int NT = BN / TY;

    extern __shared__ float sm[];
    float* Ws = sm;                    // [K][COUT]
    float* Bs = Ws + K * COUT;         // [COUT]
    float* Is = Bs + COUT;             // [BN][K+1]

    const int tid = threadIdx.x;

    for (int i = tid; i < K * COUT; i += 256) {
        int k = i / COUT, c = i % COUT;
        Ws[i] = (k < CIN) ? Wself[k * COUT + c] : Wnbr[(k - CIN) * COUT + c];
    }
    if (tid < COUT) Bs[tid] = bias[tid];

    const int base = blockIdx.x * BN;

    for (int i = tid; i < BN * K; i += 256) {
        int n = i / K, k = i % K;
        int node = base + n;
        float v;
        if (!NBR || k < CIN) v = h[node * CIN + k];
        else                 v = agg[node * CIN + (k - CIN)];
        Is[n * (K + 1) + k] = v;
    }
    __syncthreads();

    const int tx = tid % TX;
    const int ny = tid / TX;

    float acc[NT][4];
    float4 b4 = *reinterpret_cast<const float4*>(&Bs[tx * 4]);
#pragma unroll
    for (int i = 0; i < NT; i++) {
        acc[i][0] = b4.x; acc[i][1] = b4.y; acc[i][2] = b4.z; acc[i][3] = b4.w;
    }

#pragma unroll 8
    for (int k = 0; k < K; k++) {
        float4 w = *reinterpret_cast<const float4*>(&Ws[k * COUT + tx * 4]);
#pragma unroll
        for (int i = 0; i < NT; i++) {
            float v = Is[(ny * NT + i) * (K + 1) + k];
            acc[i][0] += v * w.x;
            acc[i][1] += v * w.y;
            acc[i][2] += v * w.z;
            acc[i][3] += v * w.w;
        }
    }

#pragma unroll
    for (int i = 0; i < NT; i++) {
        int node = base + ny * NT + i;
        float4 o;
        o.x = actf<ACT>(acc[i][0]);
        o.y = actf<ACT>(acc[i][1]);
        o.z = actf<ACT>(acc[i][2]);
        o.w = actf<ACT>(acc[i][3]);
        *reinterpret_cast<float4*>(&out[node * COUT + tx * 4]) = o;
    }
}

// ---------------------------------------------------------------------------
// TF32 wmma combine for the big layer: out = sigmoid([h|agg] @ [Ws;Wn] + b)
// CIN=64, COUT=128, K=128. Block = 256 threads (8 warps), BN=64 nodes.
// Warp w: node-tile = w&3 (16 rows), col-tiles = (w>>2) + 2*j, j=0..3.
// Requires K == COUT (staging buffer reuse for epilogue).
// ---------------------------------------------------------------------------
__device__ __forceinline__ float f2tf32(float x) {
    float y;
    asm("cvt.rna.tf32.f32 %0, %1;" : "=f"(y) : "f"(x));
    return y;
}

template <int CIN, int COUT, int ACT>
__global__ void wmma_combine_kernel(const float* __restrict__ h,
                                    const float* __restrict__ agg,
                                    const float* __restrict__ Wself,
                                    const float* __restrict__ Wnbr,
                                    const float* __restrict__ bias,
                                    float* __restrict__ out) {
    constexpr int K   = 2 * CIN;
    constexpr int BN  = 64;
    constexpr int LDI = K + 4;       // padded (also used as epilogue ld; K==COUT)
    constexpr int LDW = COUT + 4;
    constexpr int JT  = COUT / 32;   // col tiles per warp (4 for COUT=128)
    static_assert(K == COUT, "staging reuse requires K == COUT");

    extern __shared__ float sm[];
    float* Is = sm;                  // [BN][LDI]  inputs (tf32), later outputs
    float* Ws = Is + BN * LDI;       // [K][LDW]   weights (tf32)
    float* Bs = Ws + K * LDW;        // [COUT]

    const int tid = threadIdx.x;

    // Stage combined weight (tf32-rounded)
    for (int i = tid; i < K * COUT; i += 256) {
        int k = i / COUT, c = i % COUT;
        float w = (k < CIN) ? Wself[k * COUT + c] : Wnbr[(k - CIN) * COUT + c];
        Ws[k * LDW + c] = f2tf32(w);
    }
    if (tid < COUT) Bs[tid] = bias[tid];

    const int base = blockIdx.x * BN;

    // Stage inputs [h_row | agg_row] (tf32-rounded), float4 reads
    constexpr int Q = K / 4;        // float4 chunks per row
    for (int i = tid; i < BN * Q; i += 256) {
        int n = i / Q, q = i % Q;
        float4 v;
        if (q < CIN / 4) v = reinterpret_cast<const float4*>(h)[(base + n) * (CIN / 4) + q];
        else             v = reinterpret_cast<const float4*>(agg)[(base + n) * (CIN / 4) + (q - CIN / 4)];
        float* d = &Is[n * LDI + q * 4];
        d[0] = f2tf32(v.x); d[1] = f2tf32(v.y); d[2] = f2tf32(v.z); d[3] = f2tf32(v.w);
    }
    __syncthreads();

    const int warp  = tid >> 5;
    const int nt    = warp & 3;      // node tile (16 rows)
    const int cb    = warp >> 2;     // 0 or 1

    wmma::fragment<wmma::accumulator, 16, 16, 8, float> fc[JT];
#pragma unroll
    for (int j = 0; j < JT; j++) wmma::fill_fragment(fc[j], 0.0f);

#pragma unroll
    for (int k8 = 0; k8 < K / 8; k8++) {
        wmma::fragment<wmma::matrix_a, 16, 16, 8, wmma::precision::tf32, wmma::row_major> fa;
        wmma::load_matrix_sync(fa, &Is[nt * 16 * LDI + k8 * 8], LDI);
#pragma unroll
        for (int j = 0; j < JT; j++) {
            wmma::fragment<wmma::matrix_b, 16, 16, 8, wmma::precision::tf32, wmma::row_major> fb;
            wmma::load_matrix_sync(fb, &Ws[k8 * 8 * LDW + (cb + 2 * j) * 16], LDW);
            wmma::mma_sync(fc[j], fa, fb, fc[j]);
        }
    }
    __syncthreads();   // Is no longer needed as input

    // Stash accumulators into Is (reused as [BN][LDI] output staging)
#pragma unroll
    for (int j = 0; j < JT; j++)
        wmma::store_matrix_sync(&Is[nt * 16 * LDI + (cb + 2 * j) * 16], fc[j], LDI,
                                wmma::mem_row_major);
    __syncthreads();

    // Epilogue: bias + activation + coalesced store
    for (int i = tid; i < BN * COUT / 4; i += 256) {
        int n = i / (COUT / 4), q = i % (COUT / 4);
        float4 v = *reinterpret_cast<float4*>(&Is[n * LDI + q * 4]);
        float4 b4 = *reinterpret_cast<const float4*>(&Bs[q * 4]);
        float4 o;
        o.x = actf<ACT>(v.x + b4.x);
        o.y = actf<ACT>(v.y + b4.y);
        o.z = actf<ACT>(v.z + b4.z);
        o.w = actf<ACT>(v.w + b4.w);
        reinterpret_cast<float4*>(out)[(base + n) * (COUT / 4) + q] = o;
    }
}

// ---------------------------------------------------------------------------
// Launch
// ---------------------------------------------------------------------------
static inline int smem_bytes(int K, int COUT) {
    return (K * COUT + COUT + 64 * (K + 1)) * (int)sizeof(float);
}

extern "C" void kernel_launch(void* const* d_in, const int* in_sizes, int n_in,
                              void* d_out, int out_size) {
    const float* x     = (const float*)d_in[0];
    const int*   ei    = (const int*)d_in[1];      // [2, E]
    // d_in[2] = batch (unused)
    const float* W_lin = (const float*)d_in[3];
    const float* b_lin = (const float*)d_in[4];
    const float* Ws3   = (const float*)d_in[5];
    const float* Wn3   = (const float*)d_in[6];
    const float* b3    = (const float*)d_in[7];
    const float* Ws2   = (const float*)d_in[8];
    const float* Wn2   = (const float*)d_in[9];
    const float* b2    = (const float*)d_in[10];
    const float* Ws1   = (const float*)d_in[11];
    const float* Wn1   = (const float*)d_in[12];
    const float* b1    = (const float*)d_in[13];
    float* out = (float*)d_out;

    const int* src = ei;
    const int* dst = ei + NE;

    float *h0, *h1, *h2, *agg, *rdeg;
    int *deg, *rowoff, *cursor, *col, *bsum;
    cudaGetSymbolAddress((void**)&h0,     g_h0);
    cudaGetSymbolAddress((void**)&h1,     g_h1);
    cudaGetSymbolAddress((void**)&h2,     g_h2);
    cudaGetSymbolAddress((void**)&agg,    g_agg);
    cudaGetSymbolAddress((void**)&rdeg,   g_rdeg);
    cudaGetSymbolAddress((void**)&deg,    g_deg);
    cudaGetSymbolAddress((void**)&rowoff, g_rowoff);
    cudaGetSymbolAddress((void**)&cursor, g_cursor);
    cudaGetSymbolAddress((void**)&col,    g_col);
    cudaGetSymbolAddress((void**)&bsum,   g_bsum);

    // wmma layer1 smem: 64*132 + 128*132 + 128 floats = ~102KB
    const int wmma_smem = (64 * 132 + 128 * 132 + 128) * (int)sizeof(float);
    cudaFuncSetAttribute((const void*)wmma_combine_kernel<64, 128, 2>,
                         cudaFuncAttributeMaxDynamicSharedMemorySize, 104 * 1024);

    const int T  = 256;
    const int NB = NN / 64;          // combine grid
    const int GW = NN * 32 / T;      // gather grid (1 warp/node)

    // ---- CSR build ----
    zero2_int<<<NN / T, T>>>(deg, cursor);
    deg_kernel<<<NE / T, T>>>(dst, deg);
    scanA<<<512, 256>>>(deg, rowoff, bsum);
    scanB<<<1, 512>>>(bsum);
    scanC<<<512, 256>>>(rowoff, bsum);
    rdeg_kernel<<<NN / T, T>>>(deg, rdeg);
    fill_kernel<<<NE / T, T>>>(src, dst, rowoff, cursor, col);

    // ---- Linear(16,16) ----
    combine_kernel<16, 16, false, 0><<<NB, T, smem_bytes(16, 16)>>>(
        x, nullptr, W_lin, nullptr, b_lin, h0);

    // ---- Block3: 16 -> 32, relu ----
    gather_kernel<4><<<GW, T>>>(rowoff, deg, col, rdeg, h0, agg);
    combine_kernel<16, 32, true, 1><<<NB, T, smem_bytes(32, 32)>>>(
        h0, agg, Ws3, Wn3, b3, h1);

    // ---- Block2: 32 -> 64, relu ----
    gather_kernel<8><<<GW, T>>>(rowoff, deg, col, rdeg, h1, agg);
    combine_kernel<32, 64, true, 1><<<NB, T, smem_bytes(64, 64)>>>(
        h1, agg, Ws2, Wn2, b2, h2);

    // ---- Block1: 64 -> 128, sigmoid -> d_out (TF32 tensor cores) ----
    gather_kernel<16><<<GW, T>>>(rowoff, deg, col, rdeg, h2, agg);
    wmma_combine_kernel<64, 128, 2><<<NB, T, wmma_smem>>>(
        h2, agg, Ws1, Wn1, b1, out);
}